// round 12
// baseline (speedup 1.0000x reference)
#include <cuda_runtime.h>
#include <cuda_bf16.h>
#include <cuda_fp16.h>
#include <math.h>
#include <stdint.h>

// tcgen05 is only legal on arch-specific targets (sm_103a). The harness also
// runs a plain compute_103 PTX pass; gate the tensor kernels so that pass
// compiles a stub (never executed — exact sm_103a cubin always wins).
#if defined(__CUDA_ARCH_FEAT_SM103_ALL) || defined(__CUDA_ARCH_SPECIFIC__) || defined(__CUDA_ARCH_FAMILY_SPECIFIC__)
#define HAS_TCGEN05 1
#else
#define HAS_TCGEN05 0
#endif

#define NN 100000      // nodes
#define NE 1000000     // edges
#define F0 58
#define F1 300
#define F2 100
#define NB 98          // ceil(NN / 1024) scan blocks
#define MTILES 782     // ceil(NN / 128)
#define H2W 52         // u32 words per h2 row (50 data + 2 pad)
#define XW  30         // u32 words per packed-x row (29 data + 1 pad)

// tensor-layer padded dims
#define L1_KP 64       // K: 58 -> 64
#define L1_NP 304      // N: 300 -> 304
#define L2_KP 320      // K: 300 -> 320
#define L2_NP 104      // N: 100 -> 104

// ---------------- device scratch (allocation-free rule: static globals) ----
__device__ int      g_indeg[NN];
__device__ float    g_dis[NN];
__device__ int      g_soff[NN + 1];
__device__ int      g_cursor[NN];
__device__ int      g_bsum[NB];
__device__ uint2    g_sedge[NE];
__device__ unsigned g_xh  [(size_t)NN * XW];    // x as packed half2
__device__ float    g_agg1[(size_t)NN * F0];
__device__ unsigned g_h2b [(size_t)NN * H2W];   // h2p as packed half2
__device__ float    g_h3p [NN];
__device__ __nv_bfloat16 g_w1hi[L1_NP * L1_KP]; // atom-linearized W1^T
__device__ __nv_bfloat16 g_w1lo[L1_NP * L1_KP];
__device__ __nv_bfloat16 g_w2hi[L2_NP * L2_KP];
__device__ __nv_bfloat16 g_w2lo[L2_NP * L2_KP];

// ---------------- PTX helpers ----------------
__device__ __forceinline__ uint32_t smem_to_u32(const void* p) {
    uint32_t a;
    asm("{ .reg .u64 t; cvta.to.shared.u64 t, %1; cvt.u32.u64 %0, t; }"
        : "=r"(a) : "l"(p));
    return a;
}

#if HAS_TCGEN05
__device__ __forceinline__ uint32_t elect_one_pred() {
    uint32_t pred;
    asm volatile(
        "{\n\t.reg .pred p;\n\t"
        "elect.sync _|p, 0xFFFFFFFF;\n\t"
        "selp.b32 %0, 1, 0, p;\n\t}"
        : "=r"(pred));
    return pred;
}
#define TCGEN05_ALLOC(saddr, n) \
    asm volatile("tcgen05.alloc.cta_group::1.sync.aligned.shared::cta.b32 [%0], %1;" \
                 :: "r"((uint32_t)(saddr)), "r"((uint32_t)(n)) : "memory")
#define TCGEN05_RELINQ() \
    asm volatile("tcgen05.relinquish_alloc_permit.cta_group::1.sync.aligned;")
#define TCGEN05_DEALLOC(t, n) \
    asm volatile("tcgen05.dealloc.cta_group::1.sync.aligned.b32 %0, %1;" :: "r"(t), "r"((uint32_t)(n)))
#define TCGEN05_COMMIT(mbar) \
    asm volatile("tcgen05.commit.cta_group::1.mbarrier::arrive::one.shared::cluster.b64 [%0];" \
                 :: "r"((uint32_t)(mbar)) : "memory")
#define TCGEN05_FENCE_AFTER() asm volatile("tcgen05.fence::after_thread_sync;" ::: "memory")
#define TCGEN05_WAIT_LD()     asm volatile("tcgen05.wait::ld.sync.aligned;" ::: "memory")
#define FENCE_ASYNC()         asm volatile("fence.proxy.async.shared::cta;" ::: "memory")
#define MBARRIER_INIT(mbar, cnt) \
    asm volatile("mbarrier.init.shared.b64 [%0], %1;" :: "r"((uint32_t)(mbar)), "r"((uint32_t)(cnt)) : "memory")
#define MBARRIER_INVAL(mbar) \
    asm volatile("mbarrier.inval.shared.b64 [%0];" :: "r"((uint32_t)(mbar)) : "memory")

__device__ __forceinline__ void mbar_wait(uint32_t mbar, uint32_t parity) {
    uint32_t done;
    asm volatile(
        "{\n\t.reg .pred p;\n\t"
        "mbarrier.try_wait.parity.acquire.cta.shared::cta.b64 p, [%1], %2;\n\t"
        "selp.b32 %0, 1, 0, p;\n\t}"
        : "=r"(done) : "r"(mbar), "r"(parity) : "memory");
    if (!done) {
        asm volatile(
            "{\n\t.reg .pred P1;\n\t"
            "WAIT_LOOP_%=:\n\t"
            "mbarrier.try_wait.parity.acquire.cta.shared::cta.b64 P1, [%0], %1, 0x989680;\n\t"
            "@P1 bra.uni WAIT_DONE_%=;\n\t"
            "bra.uni WAIT_LOOP_%=;\n\t"
            "WAIT_DONE_%=:\n\t}"
            :: "r"(mbar), "r"(parity) : "memory");
    }
}

#define TCGEN05_LD_X32(r, ta) \
    asm volatile( \
        "tcgen05.ld.sync.aligned.32x32b.x32.b32 " \
        "{%0, %1, %2, %3, %4, %5, %6, %7, " \
        " %8, %9, %10, %11, %12, %13, %14, %15, " \
        " %16, %17, %18, %19, %20, %21, %22, %23, " \
        " %24, %25, %26, %27, %28, %29, %30, %31}, [%32];" \
        : "=r"((r)[0]),  "=r"((r)[1]),  "=r"((r)[2]),  "=r"((r)[3]), \
          "=r"((r)[4]),  "=r"((r)[5]),  "=r"((r)[6]),  "=r"((r)[7]), \
          "=r"((r)[8]),  "=r"((r)[9]),  "=r"((r)[10]), "=r"((r)[11]), \
          "=r"((r)[12]), "=r"((r)[13]), "=r"((r)[14]), "=r"((r)[15]), \
          "=r"((r)[16]), "=r"((r)[17]), "=r"((r)[18]), "=r"((r)[19]), \
          "=r"((r)[20]), "=r"((r)[21]), "=r"((r)[22]), "=r"((r)[23]), \
          "=r"((r)[24]), "=r"((r)[25]), "=r"((r)[26]), "=r"((r)[27]), \
          "=r"((r)[28]), "=r"((r)[29]), "=r"((r)[30]), "=r"((r)[31]) \
        : "r"(ta))
#define TCGEN05_LD_X16(r, ta) \
    asm volatile( \
        "tcgen05.ld.sync.aligned.32x32b.x16.b32 " \
        "{%0, %1, %2, %3, %4, %5, %6, %7, " \
        " %8, %9, %10, %11, %12, %13, %14, %15}, [%16];" \
        : "=r"((r)[0]),  "=r"((r)[1]),  "=r"((r)[2]),  "=r"((r)[3]), \
          "=r"((r)[4]),  "=r"((r)[5]),  "=r"((r)[6]),  "=r"((r)[7]), \
          "=r"((r)[8]),  "=r"((r)[9]),  "=r"((r)[10]), "=r"((r)[11]), \
          "=r"((r)[12]), "=r"((r)[13]), "=r"((r)[14]), "=r"((r)[15]) \
        : "r"(ta))
#define TCGEN05_LD_X8(r, ta) \
    asm volatile( \
        "tcgen05.ld.sync.aligned.32x32b.x8.b32 " \
        "{%0, %1, %2, %3, %4, %5, %6, %7}, [%8];" \
        : "=r"((r)[0]), "=r"((r)[1]), "=r"((r)[2]), "=r"((r)[3]), \
          "=r"((r)[4]), "=r"((r)[5]), "=r"((r)[6]), "=r"((r)[7]) \
        : "r"(ta))

// SS-mode cg1 bf16 MMA: D(TMEM) += A(smem desc) * B(smem desc)^T
__device__ __forceinline__ void mma_f16_ss(uint32_t d_tmem, uint64_t a_desc,
                                           uint64_t b_desc, uint32_t idesc,
                                           uint32_t en) {
    asm volatile(
        "{\n\t.reg .pred p;\n\t"
        "setp.ne.u32 p, %4, 0;\n\t"
        "tcgen05.mma.cta_group::1.kind::f16 [%0], %1, %2, %3, {%5, %5, %5, %5}, p;\n\t}"
        :: "r"(d_tmem), "l"(a_desc), "l"(b_desc), "r"(idesc), "r"(en), "r"(0u)
        : "memory");
}
#endif  // HAS_TCGEN05

static constexpr uint64_t SMEM_DESC_BASE_SW128 =
    (uint64_t(2) << 61) | (uint64_t(1) << 46) | (uint64_t(64) << 32) | (uint64_t(1) << 16);
#define MAKE_SMEM_DESC(a) (SMEM_DESC_BASE_SW128 | ((uint64_t)((a) >> 4) & 0x3FFF))
#define SWZ128(b) ((b) ^ (((b) >> 3) & 0x70))

// idesc: dtype F32(bit4) | atype BF16(bit7) | btype BF16(bit10) | N/8<<17 | M/16<<24
#define IDESC(NV) ((8u << 24) | (((NV) / 8u) << 17) | 0x490u)

__device__ __forceinline__ uint32_t pack_hf2(float a, float b) {
    __half2 p = __float22half2_rn(make_float2(a, b));
    return *(uint32_t*)&p;
}
__device__ __forceinline__ float2 unpack_hf2(unsigned u) {
    return __half22float2(*(__half2*)&u);
}

// ---------------- graph prep ----------------
// edge_index is int32 on device (JAX x64 disabled coerces int64->int32)
__global__ void k_edge_prep(const int* __restrict__ ei) {
    int e = blockIdx.x * blockDim.x + threadIdx.x;
    if (e >= NE) return;
    atomicAdd(&g_indeg[ei[NE + e]], 1);
}
// phase 1: local exclusive scan (1024/block) + block total; also emits dis
__global__ void k_scan_local() {
    __shared__ int warp_sums[32];
    const int tid = threadIdx.x;
    const int v = blockIdx.x * 1024 + tid;
    int val = (v < NN) ? g_indeg[v] : 0;
    if (v < NN) g_dis[v] = rsqrtf((float)(val + 1));   // +1 self-loop
    int x = val;
    #pragma unroll
    for (int o = 1; o < 32; o <<= 1) {
        int y = __shfl_up_sync(0xffffffffu, x, o);
        if ((tid & 31) >= o) x += y;
    }
    if ((tid & 31) == 31) warp_sums[tid >> 5] = x;
    __syncthreads();
    if (tid < 32) {
        int y = warp_sums[tid];
        #pragma unroll
        for (int o = 1; o < 32; o <<= 1) {
            int z = __shfl_up_sync(0xffffffffu, y, o);
            if (tid >= o) y += z;
        }
        warp_sums[tid] = y;
    }
    __syncthreads();
    int warp_prefix = (tid >= 32) ? warp_sums[(tid >> 5) - 1] : 0;
    if (v < NN) g_soff[v] = x + warp_prefix - val;
    if (tid == 0) g_bsum[blockIdx.x] = warp_sums[31];
}
__global__ void k_scan_bsum() {
    if (threadIdx.x == 0) {
        int run = 0;
        for (int b = 0; b < NB; b++) { int t = g_bsum[b]; g_bsum[b] = run; run += t; }
        g_soff[NN] = run;
    }
}
__global__ void k_scan_add() {
    int v = blockIdx.x * 1024 + threadIdx.x;
    if (v >= NN) return;
    int s = g_soff[v] + g_bsum[blockIdx.x];
    g_soff[v] = s;
    g_cursor[v] = s;
}
__global__ void k_scatter(const int* __restrict__ ei) {
    int e = blockIdx.x * blockDim.x + threadIdx.x;
    if (e >= NE) return;
    int r = ei[e];
    int c = ei[NE + e];
    int pos = atomicAdd(&g_cursor[c], 1);
    float nrm = g_dis[r] * g_dis[c];
    g_sedge[pos] = make_uint2((unsigned)r, __float_as_uint(nrm));
}

// ---------------- x -> packed half2 (58 = 2*29 words exactly) -------------
__global__ void k_prep_x(const float* __restrict__ x) {
    long long idx = (long long)blockIdx.x * blockDim.x + threadIdx.x;
    long long total = (long long)NN * 29;
    if (idx >= total) return;
    int v = (int)(idx / 29), w = (int)(idx % 29);
    const float* xp = x + (size_t)v * F0 + 2 * w;
    g_xh[(size_t)v * XW + w] = pack_hf2(xp[0], xp[1]);
}

// ---------------- weight prep: transpose + hi/lo split + atom-linearize ---
// B operand layout [Np rows(N), Kp cols(K)], atom = 8n x 64k (1024B):
// off = (n/8 + (k/64)*(Np/8))*512 + (n%8)*64 + (k%64)
__global__ void k_prep_w(const float* __restrict__ W, __nv_bfloat16* __restrict__ hi,
                         __nv_bfloat16* __restrict__ lo, int K, int N, int Kp, int Np) {
    int idx = blockIdx.x * blockDim.x + threadIdx.x;
    if (idx >= Kp * Np) return;
    int n = idx / Kp, k = idx % Kp;
    float v = (n < N && k < K) ? W[(size_t)k * N + n] : 0.f;
    __nv_bfloat16 h = __float2bfloat16(v);
    __nv_bfloat16 l = __float2bfloat16(v - __bfloat162float(h));
    int off = ((n >> 3) + (k >> 6) * (Np >> 3)) * 512 + (n & 7) * 64 + (k & 63);
    hi[off] = h;
    lo[off] = l;
}

// ---------------- layer-1 CSR aggregation over packed-fp16 x --------------
// agg1[v,:] = dis^2 * x[v,:] + sum_in norm * x[row,:]   (fp32 accumulate)
__global__ void k_agg1h(float* __restrict__ dst) {
    int gtid = blockIdx.x * blockDim.x + threadIdx.x;
    int v    = gtid >> 5;
    int lane = gtid & 31;
    if (v >= NN) return;
    const bool act = lane < 29;
    float2 acc = make_float2(0.f, 0.f);
    float d = g_dis[v];
    float d2 = d * d;
    if (act) {
        float2 f = unpack_hf2(g_xh[(size_t)v * XW + lane]);
        acc.x = d2 * f.x; acc.y = d2 * f.y;
    }
    int b  = g_soff[v];
    int e2 = g_soff[v + 1];
    int j = b;
    for (; j + 1 < e2; j += 2) {
        uint2 p0 = g_sedge[j];
        uint2 p1 = g_sedge[j + 1];
        float w0 = __uint_as_float(p0.y);
        float w1 = __uint_as_float(p1.y);
        if (act) {
            float2 f0 = unpack_hf2(g_xh[(size_t)p0.x * XW + lane]);
            float2 f1 = unpack_hf2(g_xh[(size_t)p1.x * XW + lane]);
            acc.x += w0 * f0.x; acc.y += w0 * f0.y;
            acc.x += w1 * f1.x; acc.y += w1 * f1.y;
        }
    }
    if (j < e2) {
        uint2 pe = g_sedge[j];
        float w = __uint_as_float(pe.y);
        if (act) {
            float2 f = unpack_hf2(g_xh[(size_t)pe.x * XW + lane]);
            acc.x += w * f.x; acc.y += w * f.y;
        }
    }
    if (act)
        *(float2*)(dst + (size_t)v * F0 + 2 * lane) = acc;
}

// ---- layer-2 aggregation (fp16 h2 rows) fused with layer-3 dot:
// h3p[v] = sum_f relu(agg2[v,f] + b2[f]) * W3[f]
__global__ void k_agg2dot(const unsigned* __restrict__ src,
                          const float* __restrict__ b2,
                          const float* __restrict__ W3) {
    int gtid = blockIdx.x * blockDim.x + threadIdx.x;
    int v    = gtid >> 5;
    int lane = gtid & 31;
    if (v >= NN) return;
    const bool hiOK = lane < 18;           // words 32..49
    float2 a0 = make_float2(0.f, 0.f), a1 = make_float2(0.f, 0.f);
    float d = g_dis[v];
    float d2 = d * d;
    const unsigned* sp = src + (size_t)v * H2W;
    {
        float2 f0 = unpack_hf2(sp[lane]);
        a0.x = d2 * f0.x; a0.y = d2 * f0.y;
        if (hiOK) {
            float2 f1 = unpack_hf2(sp[32 + lane]);
            a1.x = d2 * f1.x; a1.y = d2 * f1.y;
        }
    }
    int b  = g_soff[v];
    int e2 = g_soff[v + 1];
    int j = b;
    for (; j + 1 < e2; j += 2) {
        uint2 p0 = g_sedge[j];
        uint2 p1 = g_sedge[j + 1];
        const unsigned* s0 = src + (size_t)p0.x * H2W;
        const unsigned* s1 = src + (size_t)p1.x * H2W;
        float w0 = __uint_as_float(p0.y);
        float w1 = __uint_as_float(p1.y);
        float2 f00 = unpack_hf2(s0[lane]), f10 = unpack_hf2(s1[lane]);
        a0.x += w0 * f00.x; a0.y += w0 * f00.y;
        a0.x += w1 * f10.x; a0.y += w1 * f10.y;
        if (hiOK) {
            float2 f01 = unpack_hf2(s0[32 + lane]), f11 = unpack_hf2(s1[32 + lane]);
            a1.x += w0 * f01.x; a1.y += w0 * f01.y;
            a1.x += w1 * f11.x; a1.y += w1 * f11.y;
        }
    }
    if (j < e2) {
        uint2 pe = g_sedge[j];
        const unsigned* s0 = src + (size_t)pe.x * H2W;
        float w = __uint_as_float(pe.y);
        float2 f0 = unpack_hf2(s0[lane]);
        a0.x += w * f0.x; a0.y += w * f0.y;
        if (hiOK) {
            float2 f1 = unpack_hf2(s0[32 + lane]);
            a1.x += w * f1.x; a1.y += w * f1.y;
        }
    }
    // fused bias + relu + dot(W3) + warp reduce
    int fA = 2 * lane, fB = 64 + 2 * lane;
    float s = fmaxf(a0.x + b2[fA], 0.f) * W3[fA]
            + fmaxf(a0.y + b2[fA + 1], 0.f) * W3[fA + 1];
    if (hiOK)
        s += fmaxf(a1.x + b2[fB], 0.f) * W3[fB]
           + fmaxf(a1.y + b2[fB + 1], 0.f) * W3[fB + 1];
    #pragma unroll
    for (int o = 16; o > 0; o >>= 1)
        s += __shfl_xor_sync(0xffffffffu, s, o);
    if (lane == 0) g_h3p[v] = s;
}

// ================= Fused layer-1+2 tensor GEMM ============================
// Per CTA (128 rows):
//   D1 = agg1_tile @ W1 (TMEM 0..303)   [split-bf16, 3 products]
//   h1  = relu(D1 + b1) split hi/lo -> double-buffered A2 smem (no DRAM)
//   D2 += h1_chunk @ W2_chunk (TMEM 320..423), epilogue(c+1) overlaps MMA(c)
//   h2  = fp16(D2) -> g_h2b (packed half2 rows)
#define F_A2HI0 1024
#define F_A2LO0 17408
#define F_A2HI1 33792
#define F_A2LO1 50176
#define F_B2HI  66560
#define F_B2LO  133120
#define F_A1HI  66560
#define F_A1LO  82944
#define F_B1HI  99328
#define F_B1LO  138240
#define SMEMF   199680

__global__ void __launch_bounds__(256, 1)
k_tgemm12(const float* __restrict__ A, const float* __restrict__ b1,
          unsigned* __restrict__ Cout) {
#if HAS_TCGEN05
    extern __shared__ char smem[];
    uint32_t sb = smem_to_u32(smem);
    int tid = threadIdx.x, wid = tid >> 5, lane = tid & 31;
    int brow = blockIdx.x * 128;

    if (wid == 0) { TCGEN05_ALLOC(sb + 0, 512); TCGEN05_RELINQ(); }
    if (tid == 0) MBARRIER_INIT(sb + 8, 1);
    __syncthreads();
    uint32_t tb = *(volatile uint32_t*)smem;
    const uint32_t tD1 = tb, tD2 = tb + 320;

    // ---- phase 1 fills ----
    for (int i = tid; i < 128 * 64; i += 256) {
        int m = i >> 6, k = i & 63;
        int gm = brow + m;
        float v = (gm < NN && k < F0) ? A[(size_t)gm * F0 + k] : 0.f;
        __nv_bfloat16 h = __float2bfloat16(v);
        __nv_bfloat16 l = __float2bfloat16(v - __bfloat162float(h));
        uint32_t sw = SWZ128((uint32_t)((m << 7) + (k << 1)));
        *(__nv_bfloat16*)(smem + F_A1HI + sw) = h;
        *(__nv_bfloat16*)(smem + F_A1LO + sw) = l;
    }
    for (int i = tid; i < (L1_NP * L1_KP) / 8; i += 256) {
        uint4 h = ((const uint4*)g_w1hi)[i];
        uint4 l = ((const uint4*)g_w1lo)[i];
        uint32_t sw = SWZ128((uint32_t)(i * 16));
        *(uint4*)(smem + F_B1HI + sw) = h;
        *(uint4*)(smem + F_B1LO + sw) = l;
    }
    FENCE_ASYNC();
    __syncthreads();

    // ---- MMA1 (commit idx 0) ----
    if (wid == 0 && elect_one_pred()) {
        uint64_t ah = MAKE_SMEM_DESC(sb + F_A1HI);
        uint64_t al = MAKE_SMEM_DESC(sb + F_A1LO);
        uint64_t bh = MAKE_SMEM_DESC(sb + F_B1HI);
        uint64_t bl = MAKE_SMEM_DESC(sb + F_B1LO);
        const uint32_t id0 = IDESC(256), id1 = IDESC(48);
        #pragma unroll
        for (int s = 0; s < 4; s++) {
            uint32_t en = (s > 0);
            mma_f16_ss(tD1,       ah + 2 * s, bh + 2 * s,        id0, en);
            mma_f16_ss(tD1 + 256, ah + 2 * s, bh + 2048 + 2 * s, id1, en);
            mma_f16_ss(tD1,       ah + 2 * s, bl + 2 * s,        id0, 1);
            mma_f16_ss(tD1 + 256, ah + 2 * s, bl + 2048 + 2 * s, id1, 1);
            mma_f16_ss(tD1,       al + 2 * s, bh + 2 * s,        id0, 1);
            mma_f16_ss(tD1 + 256, al + 2 * s, bh + 2048 + 2 * s, id1, 1);
        }
        TCGEN05_COMMIT(sb + 8);
    }
    mbar_wait(sb + 8, 0);           // wait commit 0 (parity 0)
    TCGEN05_FENCE_AFTER();
    __syncthreads();                // A1/B1 dead from here

    // ---- B2 fill (overwrites phase-1 region) ----
    for (int i = tid; i < (L2_NP * L2_KP) / 8; i += 256) {
        uint4 h = ((const uint4*)g_w2hi)[i];
        uint4 l = ((const uint4*)g_w2lo)[i];
        uint32_t sw = SWZ128((uint32_t)(i * 16));
        *(uint4*)(smem + F_B2HI + sw) = h;
        *(uint4*)(smem + F_B2LO + sw) = l;
    }

    // ---- pipelined chunk loop (double-buffered A2) ----
    // commit idx for chunk c = c+1. Epilogue of chunk c (c>=2) waits commit
    // idx c-1. Waits alternate parity strictly: p0, p1, p0, p1, p0, p1.
    const uint64_t a2h[2] = { MAKE_SMEM_DESC(sb + F_A2HI0), MAKE_SMEM_DESC(sb + F_A2HI1) };
    const uint64_t a2l[2] = { MAKE_SMEM_DESC(sb + F_A2LO0), MAKE_SMEM_DESC(sb + F_A2LO1) };
    const uint64_t b2h = MAKE_SMEM_DESC(sb + F_B2HI);
    const uint64_t b2l = MAKE_SMEM_DESC(sb + F_B2LO);
    const uint32_t id2 = IDESC(104);

    for (int c = 0; c < 5; c++) {
        if (c >= 2) mbar_wait(sb + 8, (uint32_t)((c - 1) & 1));  // idx c-1
        const int buf = c & 1;
        char* a2hi_p = smem + F_A2HI0 + buf * 32768;
        char* a2lo_p = smem + F_A2LO0 + buf * 32768;
        if (wid < 4) {
            int row = wid * 32 + lane;
            uint32_t r[64];
            if (c < 4) {
                TCGEN05_LD_X32(r,      tD1 + 64 * c);
                TCGEN05_LD_X32(r + 32, tD1 + 64 * c + 32);
            } else {
                TCGEN05_LD_X32(r,      tD1 + 256);
                TCGEN05_LD_X16(r + 32, tD1 + 288);
            }
            TCGEN05_WAIT_LD();
            #pragma unroll
            for (int j = 0; j < 64; j += 2) {
                int gc = 64 * c + j;
                float v0 = (gc     < F1) ? fmaxf(__uint_as_float(r[j])     + b1[gc],     0.f) : 0.f;
                float v1 = (gc + 1 < F1) ? fmaxf(__uint_as_float(r[j + 1]) + b1[gc + 1], 0.f) : 0.f;
                __nv_bfloat16 h0 = __float2bfloat16(v0);
                __nv_bfloat16 h1b = __float2bfloat16(v1);
                __nv_bfloat16 l0 = __float2bfloat16(v0 - __bfloat162float(h0));
                __nv_bfloat16 l1 = __float2bfloat16(v1 - __bfloat162float(h1b));
                __nv_bfloat162 ph = __halves2bfloat162(h0, h1b);
                __nv_bfloat162 pl = __halves2bfloat162(l0, l1);
                uint32_t sw = SWZ128((uint32_t)((row << 7) + (j << 1)));
                *(uint32_t*)(a2hi_p + sw) = *(uint32_t*)&ph;
                *(uint32_t*)(a2lo_p + sw) = *(uint32_t*)&pl;
            }
        }
        FENCE_ASYNC();
        __syncthreads();   // A2[buf] ready; also covers B2 fill before chunk 0

        if (wid == 0 && elect_one_pred()) {
            uint32_t boff = c * 832;   // atom-col stride: 13 atoms * 1024B / 16
            #pragma unroll
            for (int s = 0; s < 4; s++) {
                uint32_t aoff = 2 * s, ko = boff + 2 * s;
                mma_f16_ss(tD2, a2h[buf] + aoff, b2h + ko, id2, (c > 0 || s > 0) ? 1u : 0u);
                mma_f16_ss(tD2, a2h[buf] + aoff, b2l + ko, id2, 1);
                mma_f16_ss(tD2, a2l[buf] + aoff, b2h + ko, id2, 1);
            }
            TCGEN05_COMMIT(sb + 8);    // commit idx c+1
        }
        // no wait here — next epilogue writes the other buffer
    }
    mbar_wait(sb + 8, 0);   // commit idx 4 (chunk 3)
    mbar_wait(sb + 8, 1);   // commit idx 5 (chunk 4)
    TCGEN05_FENCE_AFTER();
    __syncthreads();

    // ---- final epilogue: D2 -> packed half2 rows -> g_h2b ----
    uint32_t* stg = (uint32_t*)(smem + 1024);   // 128 x H2W u32 (A2 region dead)
    if (wid < 4) {
        int row = wid * 32 + lane;
        uint32_t r[32];
        #pragma unroll
        for (int g = 0; g < 3; g++) {
            TCGEN05_LD_X32(r, tD2 + g * 32);
            TCGEN05_WAIT_LD();
            #pragma unroll
            for (int j = 0; j < 32; j += 2) {
                int w = (g * 32 + j) >> 1;
                stg[row * H2W + w] = pack_hf2(__uint_as_float(r[j]),
                                              __uint_as_float(r[j + 1]));
            }
        }
        TCGEN05_LD_X8(r, tD2 + 96);
        TCGEN05_WAIT_LD();
        stg[row * H2W + 48] = pack_hf2(__uint_as_float(r[0]), __uint_as_float(r[1]));
        stg[row * H2W + 49] = pack_hf2(__uint_as_float(r[2]), __uint_as_float(r[3]));
    }
    __syncthreads();
    for (int i = tid; i < 128 * 50; i += 256) {
        int m = i / 50, w = i - m * 50;
        int gm = brow + m;
        if (gm < NN) Cout[(size_t)gm * H2W + w] = stg[m * H2W + w];
    }
    __syncthreads();
    if (tid == 0) MBARRIER_INVAL(sb + 8);
    __syncthreads();
    if (wid == 0) TCGEN05_DEALLOC(tb, 512);
#endif
}

// ---------------- final output: CSR aggregate of h3p ----------------------
__global__ void k_out_csr(float* __restrict__ out, const float* __restrict__ b3) {
    int v = blockIdx.x * blockDim.x + threadIdx.x;
    if (v >= NN) return;
    float d = g_dis[v];
    float s = d * d * g_h3p[v];
    int b  = g_soff[v];
    int e2 = g_soff[v + 1];
    for (int j = b; j < e2; j++) {
        uint2 pe = g_sedge[j];
        s += __uint_as_float(pe.y) * g_h3p[pe.x];
    }
    out[v] = s + b3[0];
}

// ---------------- launch ----------------
extern "C" void kernel_launch(void* const* d_in, const int* in_sizes, int n_in,
                              void* d_out, int out_size) {
    const float* x  = (const float*)d_in[0];
    const int*   ei = (const int*)d_in[1];
    const float* W1 = (const float*)d_in[2];
    const float* b1 = (const float*)d_in[3];
    const float* W2 = (const float*)d_in[4];
    const float* b2 = (const float*)d_in[5];
    const float* W3 = (const float*)d_in[6];
    const float* b3 = (const float*)d_in[7];
    float* out = (float*)d_out;

    const int T = 256;
    float*    agg1 = nullptr; cudaGetSymbolAddress((void**)&agg1, g_agg1);
    unsigned* h2b  = nullptr; cudaGetSymbolAddress((void**)&h2b,  g_h2b);
    int*      degp = nullptr; cudaGetSymbolAddress((void**)&degp, g_indeg);
    __nv_bfloat16 *w1h, *w1l, *w2h, *w2l;
    cudaGetSymbolAddress((void**)&w1h, g_w1hi);
    cudaGetSymbolAddress((void**)&w1l, g_w1lo);
    cudaGetSymbolAddress((void**)&w2h, g_w2hi);
    cudaGetSymbolAddress((void**)&w2l, g_w2lo);

    cudaFuncSetAttribute(k_tgemm12, cudaFuncAttributeMaxDynamicSharedMemorySize, SMEMF);

    // input/weight prep (graph-independent)
    k_prep_x<<<(unsigned)(((long long)NN * 29 + T - 1) / T), T>>>(x);
    k_prep_w<<<(L1_NP * L1_KP + T - 1) / T, T>>>(W1, w1h, w1l, F0, F1, L1_KP, L1_NP);
    k_prep_w<<<(L2_NP * L2_KP + T - 1) / T, T>>>(W2, w2h, w2l, F1, F2, L2_KP, L2_NP);

    // CSR build
    cudaMemsetAsync(degp, 0, NN * sizeof(int));
    k_edge_prep<<<(NE + T - 1) / T, T>>>(ei);
    k_scan_local<<<NB, 1024>>>();
    k_scan_bsum<<<1, 32>>>();
    k_scan_add<<<NB, 1024>>>();
    k_scatter<<<(NE + T - 1) / T, T>>>(ei);

    const unsigned aggGrid = (unsigned)(((long long)NN * 32 + T - 1) / T);

    // Layers 1+2 fused: aggregate(58, fp16 gather) -> [GEMM1+relu+GEMM2] -> h2b
    k_agg1h<<<aggGrid, T>>>(agg1);
    k_tgemm12<<<MTILES, 256, SMEMF>>>(agg1, b1, h2b);

    // Layer-2 aggregation (fp16 gather) fused with layer-3 dot, then output
    k_agg2dot<<<aggGrid, T>>>(h2b, b2, W3);
    k_out_csr<<<(NN + T - 1) / T, T>>>(out, b3);

    (void)in_sizes; (void)n_in; (void)out_size;
}

// round 13
// speedup vs baseline: 1.0735x; 1.0735x over previous
#include <cuda_runtime.h>
#include <cuda_bf16.h>
#include <cuda_fp16.h>
#include <math.h>
#include <stdint.h>

// tcgen05 is only legal on arch-specific targets (sm_103a). The harness also
// runs a plain compute_103 PTX pass; gate the tensor kernels so that pass
// compiles a stub (never executed — exact sm_103a cubin always wins).
#if defined(__CUDA_ARCH_FEAT_SM103_ALL) || defined(__CUDA_ARCH_SPECIFIC__) || defined(__CUDA_ARCH_FAMILY_SPECIFIC__)
#define HAS_TCGEN05 1
#else
#define HAS_TCGEN05 0
#endif

#define NN 100000      // nodes
#define NE 1000000     // edges
#define F0 58
#define F1 300
#define F2 100
#define NB 98          // ceil(NN / 1024) scan blocks
#define MTILES 782     // ceil(NN / 128)
#define H2W 52         // u32 words per h2 row (50 data + 2 pad)

// tensor-layer padded dims
#define L1_KP 64       // K: 58 -> 64
#define L1_NP 304      // N: 300 -> 304
#define L2_KP 320      // K: 300 -> 320
#define L2_NP 104      // N: 100 -> 104
#define W1_ELEMS (L1_NP * L1_KP)
#define W2_ELEMS (L2_NP * L2_KP)

// ---------------- device scratch (allocation-free rule: static globals) ----
__device__ int      g_indeg[NN];
__device__ float    g_dis[NN];
__device__ int      g_soff[NN + 1];
__device__ int      g_cursor[NN];
__device__ int      g_bsum[NB];
__device__ uint2    g_sedge[NE];
__device__ float    g_agg1[(size_t)NN * F0];
__device__ unsigned g_h2b [(size_t)NN * H2W];   // h2p as packed half2
__device__ float    g_h3p [NN];
__device__ __nv_bfloat16 g_w1hi[W1_ELEMS];      // atom-linearized W1^T
__device__ __nv_bfloat16 g_w1lo[W1_ELEMS];
__device__ __nv_bfloat16 g_w2hi[W2_ELEMS];
__device__ __nv_bfloat16 g_w2lo[W2_ELEMS];

// ---------------- PTX helpers ----------------
__device__ __forceinline__ uint32_t smem_to_u32(const void* p) {
    uint32_t a;
    asm("{ .reg .u64 t; cvta.to.shared.u64 t, %1; cvt.u32.u64 %0, t; }"
        : "=r"(a) : "l"(p));
    return a;
}

#if HAS_TCGEN05
__device__ __forceinline__ uint32_t elect_one_pred() {
    uint32_t pred;
    asm volatile(
        "{\n\t.reg .pred p;\n\t"
        "elect.sync _|p, 0xFFFFFFFF;\n\t"
        "selp.b32 %0, 1, 0, p;\n\t}"
        : "=r"(pred));
    return pred;
}
#define TCGEN05_ALLOC(saddr, n) \
    asm volatile("tcgen05.alloc.cta_group::1.sync.aligned.shared::cta.b32 [%0], %1;" \
                 :: "r"((uint32_t)(saddr)), "r"((uint32_t)(n)) : "memory")
#define TCGEN05_RELINQ() \
    asm volatile("tcgen05.relinquish_alloc_permit.cta_group::1.sync.aligned;")
#define TCGEN05_DEALLOC(t, n) \
    asm volatile("tcgen05.dealloc.cta_group::1.sync.aligned.b32 %0, %1;" :: "r"(t), "r"((uint32_t)(n)))
#define TCGEN05_COMMIT(mbar) \
    asm volatile("tcgen05.commit.cta_group::1.mbarrier::arrive::one.shared::cluster.b64 [%0];" \
                 :: "r"((uint32_t)(mbar)) : "memory")
#define TCGEN05_FENCE_AFTER() asm volatile("tcgen05.fence::after_thread_sync;" ::: "memory")
#define TCGEN05_WAIT_LD()     asm volatile("tcgen05.wait::ld.sync.aligned;" ::: "memory")
#define FENCE_ASYNC()         asm volatile("fence.proxy.async.shared::cta;" ::: "memory")
#define MBARRIER_INIT(mbar, cnt) \
    asm volatile("mbarrier.init.shared.b64 [%0], %1;" :: "r"((uint32_t)(mbar)), "r"((uint32_t)(cnt)) : "memory")
#define MBARRIER_INVAL(mbar) \
    asm volatile("mbarrier.inval.shared.b64 [%0];" :: "r"((uint32_t)(mbar)) : "memory")

__device__ __forceinline__ void mbar_wait(uint32_t mbar, uint32_t parity) {
    uint32_t done;
    asm volatile(
        "{\n\t.reg .pred p;\n\t"
        "mbarrier.try_wait.parity.acquire.cta.shared::cta.b64 p, [%1], %2;\n\t"
        "selp.b32 %0, 1, 0, p;\n\t}"
        : "=r"(done) : "r"(mbar), "r"(parity) : "memory");
    if (!done) {
        asm volatile(
            "{\n\t.reg .pred P1;\n\t"
            "WAIT_LOOP_%=:\n\t"
            "mbarrier.try_wait.parity.acquire.cta.shared::cta.b64 P1, [%0], %1, 0x989680;\n\t"
            "@P1 bra.uni WAIT_DONE_%=;\n\t"
            "bra.uni WAIT_LOOP_%=;\n\t"
            "WAIT_DONE_%=:\n\t}"
            :: "r"(mbar), "r"(parity) : "memory");
    }
}

#define TCGEN05_LD_X32(r, ta) \
    asm volatile( \
        "tcgen05.ld.sync.aligned.32x32b.x32.b32 " \
        "{%0, %1, %2, %3, %4, %5, %6, %7, " \
        " %8, %9, %10, %11, %12, %13, %14, %15, " \
        " %16, %17, %18, %19, %20, %21, %22, %23, " \
        " %24, %25, %26, %27, %28, %29, %30, %31}, [%32];" \
        : "=r"((r)[0]),  "=r"((r)[1]),  "=r"((r)[2]),  "=r"((r)[3]), \
          "=r"((r)[4]),  "=r"((r)[5]),  "=r"((r)[6]),  "=r"((r)[7]), \
          "=r"((r)[8]),  "=r"((r)[9]),  "=r"((r)[10]), "=r"((r)[11]), \
          "=r"((r)[12]), "=r"((r)[13]), "=r"((r)[14]), "=r"((r)[15]), \
          "=r"((r)[16]), "=r"((r)[17]), "=r"((r)[18]), "=r"((r)[19]), \
          "=r"((r)[20]), "=r"((r)[21]), "=r"((r)[22]), "=r"((r)[23]), \
          "=r"((r)[24]), "=r"((r)[25]), "=r"((r)[26]), "=r"((r)[27]), \
          "=r"((r)[28]), "=r"((r)[29]), "=r"((r)[30]), "=r"((r)[31]) \
        : "r"(ta))
#define TCGEN05_LD_X16(r, ta) \
    asm volatile( \
        "tcgen05.ld.sync.aligned.32x32b.x16.b32 " \
        "{%0, %1, %2, %3, %4, %5, %6, %7, " \
        " %8, %9, %10, %11, %12, %13, %14, %15}, [%16];" \
        : "=r"((r)[0]),  "=r"((r)[1]),  "=r"((r)[2]),  "=r"((r)[3]), \
          "=r"((r)[4]),  "=r"((r)[5]),  "=r"((r)[6]),  "=r"((r)[7]), \
          "=r"((r)[8]),  "=r"((r)[9]),  "=r"((r)[10]), "=r"((r)[11]), \
          "=r"((r)[12]), "=r"((r)[13]), "=r"((r)[14]), "=r"((r)[15]) \
        : "r"(ta))
#define TCGEN05_LD_X8(r, ta) \
    asm volatile( \
        "tcgen05.ld.sync.aligned.32x32b.x8.b32 " \
        "{%0, %1, %2, %3, %4, %5, %6, %7}, [%8];" \
        : "=r"((r)[0]), "=r"((r)[1]), "=r"((r)[2]), "=r"((r)[3]), \
          "=r"((r)[4]), "=r"((r)[5]), "=r"((r)[6]), "=r"((r)[7]) \
        : "r"(ta))

// SS-mode cg1 bf16 MMA: D(TMEM) += A(smem desc) * B(smem desc)^T
__device__ __forceinline__ void mma_f16_ss(uint32_t d_tmem, uint64_t a_desc,
                                           uint64_t b_desc, uint32_t idesc,
                                           uint32_t en) {
    asm volatile(
        "{\n\t.reg .pred p;\n\t"
        "setp.ne.u32 p, %4, 0;\n\t"
        "tcgen05.mma.cta_group::1.kind::f16 [%0], %1, %2, %3, {%5, %5, %5, %5}, p;\n\t}"
        :: "r"(d_tmem), "l"(a_desc), "l"(b_desc), "r"(idesc), "r"(en), "r"(0u)
        : "memory");
}
#endif  // HAS_TCGEN05

static constexpr uint64_t SMEM_DESC_BASE_SW128 =
    (uint64_t(2) << 61) | (uint64_t(1) << 46) | (uint64_t(64) << 32) | (uint64_t(1) << 16);
#define MAKE_SMEM_DESC(a) (SMEM_DESC_BASE_SW128 | ((uint64_t)((a) >> 4) & 0x3FFF))
#define SWZ128(b) ((b) ^ (((b) >> 3) & 0x70))

// idesc: dtype F32(bit4) | atype BF16(bit7) | btype BF16(bit10) | N/8<<17 | M/16<<24
#define IDESC(NV) ((8u << 24) | (((NV) / 8u) << 17) | 0x490u)

__device__ __forceinline__ uint32_t pack_hf2(float a, float b) {
    __half2 p = __float22half2_rn(make_float2(a, b));
    return *(uint32_t*)&p;
}
__device__ __forceinline__ float2 unpack_hf2(unsigned u) {
    return __half22float2(*(__half2*)&u);
}

// ---------------- graph prep ----------------
// edge_index is int32 on device (JAX x64 disabled coerces int64->int32)
__global__ void k_edge_prep(const int* __restrict__ ei) {
    int e = blockIdx.x * blockDim.x + threadIdx.x;
    if (e >= NE) return;
    atomicAdd(&g_indeg[ei[NE + e]], 1);
}
// phase 1: local exclusive scan (1024/block) + block total; also emits dis
__global__ void k_scan_local() {
    __shared__ int warp_sums[32];
    const int tid = threadIdx.x;
    const int v = blockIdx.x * 1024 + tid;
    int val = (v < NN) ? g_indeg[v] : 0;
    if (v < NN) g_dis[v] = rsqrtf((float)(val + 1));   // +1 self-loop
    int x = val;
    #pragma unroll
    for (int o = 1; o < 32; o <<= 1) {
        int y = __shfl_up_sync(0xffffffffu, x, o);
        if ((tid & 31) >= o) x += y;
    }
    if ((tid & 31) == 31) warp_sums[tid >> 5] = x;
    __syncthreads();
    if (tid < 32) {
        int y = warp_sums[tid];
        #pragma unroll
        for (int o = 1; o < 32; o <<= 1) {
            int z = __shfl_up_sync(0xffffffffu, y, o);
            if (tid >= o) y += z;
        }
        warp_sums[tid] = y;
    }
    __syncthreads();
    int warp_prefix = (tid >= 32) ? warp_sums[(tid >> 5) - 1] : 0;
    if (v < NN) g_soff[v] = x + warp_prefix - val;
    if (tid == 0) g_bsum[blockIdx.x] = warp_sums[31];
}
__global__ void k_scan_bsum() {
    if (threadIdx.x == 0) {
        int run = 0;
        for (int b = 0; b < NB; b++) { int t = g_bsum[b]; g_bsum[b] = run; run += t; }
        g_soff[NN] = run;
    }
}
__global__ void k_scan_add() {
    int v = blockIdx.x * 1024 + threadIdx.x;
    if (v >= NN) return;
    int s = g_soff[v] + g_bsum[blockIdx.x];
    g_soff[v] = s;
    g_cursor[v] = s;
}
__global__ void k_scatter(const int* __restrict__ ei) {
    int e = blockIdx.x * blockDim.x + threadIdx.x;
    if (e >= NE) return;
    int r = ei[e];
    int c = ei[NE + e];
    int pos = atomicAdd(&g_cursor[c], 1);
    float nrm = g_dis[r] * g_dis[c];
    g_sedge[pos] = make_uint2((unsigned)r, __float_as_uint(nrm));
}

// ---------------- weight prep (both layers in one launch) -----------------
// B operand layout [Np rows(N), Kp cols(K)], atom = 8n x 64k (1024B):
// off = (n/8 + (k/64)*(Np/8))*512 + (n%8)*64 + (k%64)
__global__ void k_prep_w(const float* __restrict__ W1, const float* __restrict__ W2) {
    int idx = blockIdx.x * blockDim.x + threadIdx.x;
    const float* W;
    __nv_bfloat16 *hi, *lo;
    int K, N, Kp, Np;
    if (idx < W1_ELEMS) {
        W = W1; hi = g_w1hi; lo = g_w1lo; K = F0; N = F1; Kp = L1_KP; Np = L1_NP;
    } else if (idx < W1_ELEMS + W2_ELEMS) {
        idx -= W1_ELEMS;
        W = W2; hi = g_w2hi; lo = g_w2lo; K = F1; N = F2; Kp = L2_KP; Np = L2_NP;
    } else return;
    int n = idx / Kp, k = idx % Kp;
    float v = (n < N && k < K) ? W[(size_t)k * N + n] : 0.f;
    __nv_bfloat16 h = __float2bfloat16(v);
    __nv_bfloat16 l = __float2bfloat16(v - __bfloat162float(h));
    int off = ((n >> 3) + (k >> 6) * (Np >> 3)) * 512 + (n & 7) * 64 + (k & 63);
    hi[off] = h;
    lo[off] = l;
}

// ---------------- CSR aggregation (layer 1, fp32 x): -----------------------
template <int F>
__global__ void k_agg_csr(const float* __restrict__ src, float* __restrict__ dst) {
    int gtid = blockIdx.x * blockDim.x + threadIdx.x;
    int v    = gtid >> 5;
    int lane = gtid & 31;
    if (v >= NN) return;
    constexpr int NA = (F + 31) / 32;
    float acc[NA];
    float d = g_dis[v];
    const float* selfp = src + (size_t)v * F;
    #pragma unroll
    for (int i = 0; i < NA; i++) {
        int f = lane + 32 * i;
        acc[i] = (f < F) ? d * d * selfp[f] : 0.f;
    }
    int b  = g_soff[v];
    int e2 = g_soff[v + 1];
    int j = b;
    for (; j + 1 < e2; j += 2) {           // 2-edge unroll
        uint2 p0 = g_sedge[j];
        uint2 p1 = g_sedge[j + 1];
        const float* s0 = src + (size_t)p0.x * F;
        const float* s1 = src + (size_t)p1.x * F;
        float w0 = __uint_as_float(p0.y);
        float w1 = __uint_as_float(p1.y);
        #pragma unroll
        for (int i = 0; i < NA; i++) {
            int f = lane + 32 * i;
            if (f < F) {
                float a0 = s0[f], a1 = s1[f];
                acc[i] += w0 * a0;
                acc[i] += w1 * a1;
            }
        }
    }
    if (j < e2) {
        uint2 pe = g_sedge[j];
        const float* sp = src + (size_t)pe.x * F;
        float w = __uint_as_float(pe.y);
        #pragma unroll
        for (int i = 0; i < NA; i++) {
            int f = lane + 32 * i;
            if (f < F) acc[i] += w * sp[f];
        }
    }
    float* dp = dst + (size_t)v * F;
    #pragma unroll
    for (int i = 0; i < NA; i++) {
        int f = lane + 32 * i;
        if (f < F) dp[f] = acc[i];
    }
}

// ---- layer-2 aggregation (fp16 h2 rows) fused with layer-3 dot (4-unroll):
// h3p[v] = sum_f relu(agg2[v,f] + b2[f]) * W3[f]
__global__ void k_agg2dot(const unsigned* __restrict__ src,
                          const float* __restrict__ b2,
                          const float* __restrict__ W3) {
    int gtid = blockIdx.x * blockDim.x + threadIdx.x;
    int v    = gtid >> 5;
    int lane = gtid & 31;
    if (v >= NN) return;
    const bool hiOK = lane < 18;           // words 32..49
    float2 a0 = make_float2(0.f, 0.f), a1 = make_float2(0.f, 0.f);
    float d = g_dis[v];
    float d2 = d * d;
    const unsigned* sp = src + (size_t)v * H2W;
    {
        float2 f0 = unpack_hf2(sp[lane]);
        a0.x = d2 * f0.x; a0.y = d2 * f0.y;
        if (hiOK) {
            float2 f1 = unpack_hf2(sp[32 + lane]);
            a1.x = d2 * f1.x; a1.y = d2 * f1.y;
        }
    }
    int b  = g_soff[v];
    int e2 = g_soff[v + 1];
    int j = b;
    for (; j + 3 < e2; j += 4) {           // 4-edge unroll: MLP 4
        uint2 p0 = g_sedge[j],     p1 = g_sedge[j + 1];
        uint2 p2 = g_sedge[j + 2], p3 = g_sedge[j + 3];
        const unsigned* s0 = src + (size_t)p0.x * H2W;
        const unsigned* s1 = src + (size_t)p1.x * H2W;
        const unsigned* s2 = src + (size_t)p2.x * H2W;
        const unsigned* s3 = src + (size_t)p3.x * H2W;
        float w0 = __uint_as_float(p0.y), w1 = __uint_as_float(p1.y);
        float w2 = __uint_as_float(p2.y), w3 = __uint_as_float(p3.y);
        unsigned u0 = s0[lane], u1 = s1[lane], u2 = s2[lane], u3 = s3[lane];
        float2 f0 = unpack_hf2(u0), f1 = unpack_hf2(u1);
        float2 f2 = unpack_hf2(u2), f3 = unpack_hf2(u3);
        a0.x += w0 * f0.x; a0.y += w0 * f0.y;
        a0.x += w1 * f1.x; a0.y += w1 * f1.y;
        a0.x += w2 * f2.x; a0.y += w2 * f2.y;
        a0.x += w3 * f3.x; a0.y += w3 * f3.y;
        if (hiOK) {
            unsigned q0 = s0[32 + lane], q1 = s1[32 + lane];
            unsigned q2 = s2[32 + lane], q3 = s3[32 + lane];
            float2 g0 = unpack_hf2(q0), g1 = unpack_hf2(q1);
            float2 g2 = unpack_hf2(q2), g3 = unpack_hf2(q3);
            a1.x += w0 * g0.x; a1.y += w0 * g0.y;
            a1.x += w1 * g1.x; a1.y += w1 * g1.y;
            a1.x += w2 * g2.x; a1.y += w2 * g2.y;
            a1.x += w3 * g3.x; a1.y += w3 * g3.y;
        }
    }
    for (; j < e2; j++) {
        uint2 pe = g_sedge[j];
        const unsigned* s0 = src + (size_t)pe.x * H2W;
        float w = __uint_as_float(pe.y);
        float2 f0 = unpack_hf2(s0[lane]);
        a0.x += w * f0.x; a0.y += w * f0.y;
        if (hiOK) {
            float2 f1 = unpack_hf2(s0[32 + lane]);
            a1.x += w * f1.x; a1.y += w * f1.y;
        }
    }
    // fused bias + relu + dot(W3) + warp reduce
    int fA = 2 * lane, fB = 64 + 2 * lane;
    float s = fmaxf(a0.x + b2[fA], 0.f) * W3[fA]
            + fmaxf(a0.y + b2[fA + 1], 0.f) * W3[fA + 1];
    if (hiOK)
        s += fmaxf(a1.x + b2[fB], 0.f) * W3[fB]
           + fmaxf(a1.y + b2[fB + 1], 0.f) * W3[fB + 1];
    #pragma unroll
    for (int o = 16; o > 0; o >>= 1)
        s += __shfl_xor_sync(0xffffffffu, s, o);
    if (lane == 0) g_h3p[v] = s;
}

// ================= Fused layer-1+2 tensor GEMM ============================
// Per CTA (128 rows):
//   D1 = agg1_tile @ W1 (TMEM 0..303)   [split-bf16, 3 products]
//   h1  = relu(D1 + b1) split hi/lo -> double-buffered A2 smem (no DRAM)
//   D2 += h1_chunk @ W2_chunk (TMEM 320..423), epilogue(c+1) overlaps MMA(c)
//   h2  = fp16(D2) -> g_h2b (packed half2 rows)
#define F_A2HI0 1024
#define F_A2LO0 17408
#define F_A2HI1 33792
#define F_A2LO1 50176
#define F_B2HI  66560
#define F_B2LO  133120
#define F_A1HI  66560
#define F_A1LO  82944
#define F_B1HI  99328
#define F_B1LO  138240
#define SMEMF   199680

__global__ void __launch_bounds__(256, 1)
k_tgemm12(const float* __restrict__ A, const float* __restrict__ b1,
          unsigned* __restrict__ Cout) {
#if HAS_TCGEN05
    extern __shared__ char smem[];
    uint32_t sb = smem_to_u32(smem);
    int tid = threadIdx.x, wid = tid >> 5, lane = tid & 31;
    int brow = blockIdx.x * 128;

    if (wid == 0) { TCGEN05_ALLOC(sb + 0, 512); TCGEN05_RELINQ(); }
    if (tid == 0) MBARRIER_INIT(sb + 8, 1);
    __syncthreads();
    uint32_t tb = *(volatile uint32_t*)smem;
    const uint32_t tD1 = tb, tD2 = tb + 320;

    // ---- phase 1 fills ----
    for (int i = tid; i < 128 * 64; i += 256) {
        int m = i >> 6, k = i & 63;
        int gm = brow + m;
        float v = (gm < NN && k < F0) ? A[(size_t)gm * F0 + k] : 0.f;
        __nv_bfloat16 h = __float2bfloat16(v);
        __nv_bfloat16 l = __float2bfloat16(v - __bfloat162float(h));
        uint32_t sw = SWZ128((uint32_t)((m << 7) + (k << 1)));
        *(__nv_bfloat16*)(smem + F_A1HI + sw) = h;
        *(__nv_bfloat16*)(smem + F_A1LO + sw) = l;
    }
    for (int i = tid; i < W1_ELEMS / 8; i += 256) {
        uint4 h = ((const uint4*)g_w1hi)[i];
        uint4 l = ((const uint4*)g_w1lo)[i];
        uint32_t sw = SWZ128((uint32_t)(i * 16));
        *(uint4*)(smem + F_B1HI + sw) = h;
        *(uint4*)(smem + F_B1LO + sw) = l;
    }
    FENCE_ASYNC();
    __syncthreads();

    // ---- MMA1 (commit idx 0) ----
    if (wid == 0 && elect_one_pred()) {
        uint64_t ah = MAKE_SMEM_DESC(sb + F_A1HI);
        uint64_t al = MAKE_SMEM_DESC(sb + F_A1LO);
        uint64_t bh = MAKE_SMEM_DESC(sb + F_B1HI);
        uint64_t bl = MAKE_SMEM_DESC(sb + F_B1LO);
        const uint32_t id0 = IDESC(256), id1 = IDESC(48);
        #pragma unroll
        for (int s = 0; s < 4; s++) {
            uint32_t en = (s > 0);
            mma_f16_ss(tD1,       ah + 2 * s, bh + 2 * s,        id0, en);
            mma_f16_ss(tD1 + 256, ah + 2 * s, bh + 2048 + 2 * s, id1, en);
            mma_f16_ss(tD1,       ah + 2 * s, bl + 2 * s,        id0, 1);
            mma_f16_ss(tD1 + 256, ah + 2 * s, bl + 2048 + 2 * s, id1, 1);
            mma_f16_ss(tD1,       al + 2 * s, bh + 2 * s,        id0, 1);
            mma_f16_ss(tD1 + 256, al + 2 * s, bh + 2048 + 2 * s, id1, 1);
        }
        TCGEN05_COMMIT(sb + 8);
    }
    mbar_wait(sb + 8, 0);           // wait commit 0 (parity 0)
    TCGEN05_FENCE_AFTER();
    __syncthreads();                // A1/B1 dead from here

    // ---- B2 fill (overwrites phase-1 region) ----
    for (int i = tid; i < W2_ELEMS / 8; i += 256) {
        uint4 h = ((const uint4*)g_w2hi)[i];
        uint4 l = ((const uint4*)g_w2lo)[i];
        uint32_t sw = SWZ128((uint32_t)(i * 16));
        *(uint4*)(smem + F_B2HI + sw) = h;
        *(uint4*)(smem + F_B2LO + sw) = l;
    }

    // ---- pipelined chunk loop (double-buffered A2) ----
    // commit idx for chunk c = c+1. Epilogue of chunk c (c>=2) waits commit
    // idx c-1. Waits alternate parity strictly: p0, p1, p0, p1, p0, p1.
    const uint64_t a2h[2] = { MAKE_SMEM_DESC(sb + F_A2HI0), MAKE_SMEM_DESC(sb + F_A2HI1) };
    const uint64_t a2l[2] = { MAKE_SMEM_DESC(sb + F_A2LO0), MAKE_SMEM_DESC(sb + F_A2LO1) };
    const uint64_t b2h = MAKE_SMEM_DESC(sb + F_B2HI);
    const uint64_t b2l = MAKE_SMEM_DESC(sb + F_B2LO);
    const uint32_t id2 = IDESC(104);

    for (int c = 0; c < 5; c++) {
        if (c >= 2) mbar_wait(sb + 8, (uint32_t)((c - 1) & 1));  // idx c-1
        const int buf = c & 1;
        char* a2hi_p = smem + F_A2HI0 + buf * 32768;
        char* a2lo_p = smem + F_A2LO0 + buf * 32768;
        if (wid < 4) {
            int row = wid * 32 + lane;
            uint32_t r[64];
            if (c < 4) {
                TCGEN05_LD_X32(r,      tD1 + 64 * c);
                TCGEN05_LD_X32(r + 32, tD1 + 64 * c + 32);
            } else {
                TCGEN05_LD_X32(r,      tD1 + 256);
                TCGEN05_LD_X16(r + 32, tD1 + 288);
            }
            TCGEN05_WAIT_LD();
            #pragma unroll
            for (int j = 0; j < 64; j += 2) {
                int gc = 64 * c + j;
                float v0 = (gc     < F1) ? fmaxf(__uint_as_float(r[j])     + b1[gc],     0.f) : 0.f;
                float v1 = (gc + 1 < F1) ? fmaxf(__uint_as_float(r[j + 1]) + b1[gc + 1], 0.f) : 0.f;
                __nv_bfloat16 h0 = __float2bfloat16(v0);
                __nv_bfloat16 h1b = __float2bfloat16(v1);
                __nv_bfloat16 l0 = __float2bfloat16(v0 - __bfloat162float(h0));
                __nv_bfloat16 l1 = __float2bfloat16(v1 - __bfloat162float(h1b));
                __nv_bfloat162 ph = __halves2bfloat162(h0, h1b);
                __nv_bfloat162 pl = __halves2bfloat162(l0, l1);
                uint32_t sw = SWZ128((uint32_t)((row << 7) + (j << 1)));
                *(uint32_t*)(a2hi_p + sw) = *(uint32_t*)&ph;
                *(uint32_t*)(a2lo_p + sw) = *(uint32_t*)&pl;
            }
        }
        FENCE_ASYNC();
        __syncthreads();   // A2[buf] ready; also covers B2 fill before chunk 0

        if (wid == 0 && elect_one_pred()) {
            uint32_t boff = c * 832;   // atom-col stride: 13 atoms * 1024B / 16
            #pragma unroll
            for (int s = 0; s < 4; s++) {
                uint32_t aoff = 2 * s, ko = boff + 2 * s;
                mma_f16_ss(tD2, a2h[buf] + aoff, b2h + ko, id2, (c > 0 || s > 0) ? 1u : 0u);
                mma_f16_ss(tD2, a2h[buf] + aoff, b2l + ko, id2, 1);
                mma_f16_ss(tD2, a2l[buf] + aoff, b2h + ko, id2, 1);
            }
            TCGEN05_COMMIT(sb + 8);    // commit idx c+1
        }
        // no wait here — next epilogue writes the other buffer
    }
    mbar_wait(sb + 8, 0);   // commit idx 4 (chunk 3)
    mbar_wait(sb + 8, 1);   // commit idx 5 (chunk 4)
    TCGEN05_FENCE_AFTER();
    __syncthreads();

    // ---- final epilogue: D2 -> packed half2 rows -> g_h2b ----
    uint32_t* stg = (uint32_t*)(smem + 1024);   // 128 x H2W u32 (A2 region dead)
    if (wid < 4) {
        int row = wid * 32 + lane;
        uint32_t r[32];
        #pragma unroll
        for (int g = 0; g < 3; g++) {
            TCGEN05_LD_X32(r, tD2 + g * 32);
            TCGEN05_WAIT_LD();
            #pragma unroll
            for (int j = 0; j < 32; j += 2) {
                int w = (g * 32 + j) >> 1;
                stg[row * H2W + w] = pack_hf2(__uint_as_float(r[j]),
                                              __uint_as_float(r[j + 1]));
            }
        }
        TCGEN05_LD_X8(r, tD2 + 96);
        TCGEN05_WAIT_LD();
        stg[row * H2W + 48] = pack_hf2(__uint_as_float(r[0]), __uint_as_float(r[1]));
        stg[row * H2W + 49] = pack_hf2(__uint_as_float(r[2]), __uint_as_float(r[3]));
    }
    __syncthreads();
    for (int i = tid; i < 128 * 50; i += 256) {
        int m = i / 50, w = i - m * 50;
        int gm = brow + m;
        if (gm < NN) Cout[(size_t)gm * H2W + w] = stg[m * H2W + w];
    }
    __syncthreads();
    if (tid == 0) MBARRIER_INVAL(sb + 8);
    __syncthreads();
    if (wid == 0) TCGEN05_DEALLOC(tb, 512);
#endif
}

// ---------------- final output: CSR aggregate of h3p ----------------------
__global__ void k_out_csr(float* __restrict__ out, const float* __restrict__ b3) {
    int v = blockIdx.x * blockDim.x + threadIdx.x;
    if (v >= NN) return;
    float d = g_dis[v];
    float s = d * d * g_h3p[v];
    int b  = g_soff[v];
    int e2 = g_soff[v + 1];
    for (int j = b; j < e2; j++) {
        uint2 pe = g_sedge[j];
        s += __uint_as_float(pe.y) * g_h3p[pe.x];
    }
    out[v] = s + b3[0];
}

// ---------------- launch ----------------
extern "C" void kernel_launch(void* const* d_in, const int* in_sizes, int n_in,
                              void* d_out, int out_size) {
    const float* x  = (const float*)d_in[0];
    const int*   ei = (const int*)d_in[1];
    const float* W1 = (const float*)d_in[2];
    const float* b1 = (const float*)d_in[3];
    const float* W2 = (const float*)d_in[4];
    const float* b2 = (const float*)d_in[5];
    const float* W3 = (const float*)d_in[6];
    const float* b3 = (const float*)d_in[7];
    float* out = (float*)d_out;

    const int T = 256;
    float*    agg1 = nullptr; cudaGetSymbolAddress((void**)&agg1, g_agg1);
    unsigned* h2b  = nullptr; cudaGetSymbolAddress((void**)&h2b,  g_h2b);
    int*      degp = nullptr; cudaGetSymbolAddress((void**)&degp, g_indeg);

    cudaFuncSetAttribute(k_tgemm12, cudaFuncAttributeMaxDynamicSharedMemorySize, SMEMF);

    // weight prep (both layers, one launch; graph-independent)
    k_prep_w<<<(W1_ELEMS + W2_ELEMS + T - 1) / T, T>>>(W1, W2);

    // CSR build
    cudaMemsetAsync(degp, 0, NN * sizeof(int));
    k_edge_prep<<<(NE + T - 1) / T, T>>>(ei);
    k_scan_local<<<NB, 1024>>>();
    k_scan_bsum<<<1, 32>>>();
    k_scan_add<<<NB, 1024>>>();
    k_scatter<<<(NE + T - 1) / T, T>>>(ei);

    const unsigned aggGrid = (unsigned)(((long long)NN * 32 + T - 1) / T);

    // Layers 1+2 fused: aggregate(58, fp32 gather) -> [GEMM1+relu+GEMM2] -> h2b
    k_agg_csr<F0><<<aggGrid, T>>>(x, agg1);
    k_tgemm12<<<MTILES, 256, SMEMF>>>(agg1, b1, h2b);

    // Layer-2 aggregation (fp16 gather, 4-edge unroll) fused with layer-3 dot
    k_agg2dot<<<aggGrid, T>>>(h2b, b2, W3);
    k_out_csr<<<(NN + T - 1) / T, T>>>(out, b3);

    (void)in_sizes; (void)n_in; (void)out_size;
}

// round 14
// speedup vs baseline: 1.0870x; 1.0125x over previous
#include <cuda_runtime.h>
#include <cuda_bf16.h>
#include <cuda_fp16.h>
#include <math.h>
#include <stdint.h>

// tcgen05 is only legal on arch-specific targets (sm_103a). The harness also
// runs a plain compute_103 PTX pass; gate the tensor kernels so that pass
// compiles a stub (never executed — exact sm_103a cubin always wins).
#if defined(__CUDA_ARCH_FEAT_SM103_ALL) || defined(__CUDA_ARCH_SPECIFIC__) || defined(__CUDA_ARCH_FAMILY_SPECIFIC__)
#define HAS_TCGEN05 1
#else
#define HAS_TCGEN05 0
#endif

#define NN 100000      // nodes
#define NE 1000000     // edges
#define F0 58
#define F1 300
#define F2 100
#define NB 98          // ceil(NN / 1024) scan blocks
#define MTILES 782     // ceil(NN / 128)
#define H2W 52         // u32 words per h2 row (50 data + 2 pad)

// tensor-layer padded dims
#define L1_KP 64       // K: 58 -> 64
#define L1_NP 304      // N: 300 -> 304
#define L2_KP 320      // K: 300 -> 320
#define L2_NP 104      // N: 100 -> 104
#define W1_ELEMS (L1_NP * L1_KP)
#define W2_ELEMS (L2_NP * L2_KP)

// ---------------- device scratch (allocation-free rule: static globals) ----
__device__ int      g_indeg[NN];
__device__ float    g_dis[NN];
__device__ int      g_soff[NN + 1];
__device__ int      g_cursor[NN];
__device__ int      g_bsum[NB];
__device__ uint2    g_sedge[NE];
__device__ float    g_agg1[(size_t)NN * F0];
__device__ unsigned g_h2b [(size_t)NN * H2W];   // h2p as packed half2
__device__ float    g_h3p [NN];
__device__ __nv_bfloat16 g_w1hi[W1_ELEMS];      // atom-linearized W1^T
__device__ __nv_bfloat16 g_w1lo[W1_ELEMS];
__device__ __nv_bfloat16 g_w2hi[W2_ELEMS];
__device__ __nv_bfloat16 g_w2lo[W2_ELEMS];

// ---------------- PTX helpers ----------------
__device__ __forceinline__ uint32_t smem_to_u32(const void* p) {
    uint32_t a;
    asm("{ .reg .u64 t; cvta.to.shared.u64 t, %1; cvt.u32.u64 %0, t; }"
        : "=r"(a) : "l"(p));
    return a;
}

#if HAS_TCGEN05
__device__ __forceinline__ uint32_t elect_one_pred() {
    uint32_t pred;
    asm volatile(
        "{\n\t.reg .pred p;\n\t"
        "elect.sync _|p, 0xFFFFFFFF;\n\t"
        "selp.b32 %0, 1, 0, p;\n\t}"
        : "=r"(pred));
    return pred;
}
#define TCGEN05_ALLOC(saddr, n) \
    asm volatile("tcgen05.alloc.cta_group::1.sync.aligned.shared::cta.b32 [%0], %1;" \
                 :: "r"((uint32_t)(saddr)), "r"((uint32_t)(n)) : "memory")
#define TCGEN05_RELINQ() \
    asm volatile("tcgen05.relinquish_alloc_permit.cta_group::1.sync.aligned;")
#define TCGEN05_DEALLOC(t, n) \
    asm volatile("tcgen05.dealloc.cta_group::1.sync.aligned.b32 %0, %1;" :: "r"(t), "r"((uint32_t)(n)))
#define TCGEN05_COMMIT(mbar) \
    asm volatile("tcgen05.commit.cta_group::1.mbarrier::arrive::one.shared::cluster.b64 [%0];" \
                 :: "r"((uint32_t)(mbar)) : "memory")
#define TCGEN05_FENCE_AFTER() asm volatile("tcgen05.fence::after_thread_sync;" ::: "memory")
#define TCGEN05_WAIT_LD()     asm volatile("tcgen05.wait::ld.sync.aligned;" ::: "memory")
#define FENCE_ASYNC()         asm volatile("fence.proxy.async.shared::cta;" ::: "memory")
#define MBARRIER_INIT(mbar, cnt) \
    asm volatile("mbarrier.init.shared.b64 [%0], %1;" :: "r"((uint32_t)(mbar)), "r"((uint32_t)(cnt)) : "memory")
#define MBARRIER_INVAL(mbar) \
    asm volatile("mbarrier.inval.shared.b64 [%0];" :: "r"((uint32_t)(mbar)) : "memory")

__device__ __forceinline__ void mbar_wait(uint32_t mbar, uint32_t parity) {
    uint32_t done;
    asm volatile(
        "{\n\t.reg .pred p;\n\t"
        "mbarrier.try_wait.parity.acquire.cta.shared::cta.b64 p, [%1], %2;\n\t"
        "selp.b32 %0, 1, 0, p;\n\t}"
        : "=r"(done) : "r"(mbar), "r"(parity) : "memory");
    if (!done) {
        asm volatile(
            "{\n\t.reg .pred P1;\n\t"
            "WAIT_LOOP_%=:\n\t"
            "mbarrier.try_wait.parity.acquire.cta.shared::cta.b64 P1, [%0], %1, 0x989680;\n\t"
            "@P1 bra.uni WAIT_DONE_%=;\n\t"
            "bra.uni WAIT_LOOP_%=;\n\t"
            "WAIT_DONE_%=:\n\t}"
            :: "r"(mbar), "r"(parity) : "memory");
    }
}

#define TCGEN05_LD_X32(r, ta) \
    asm volatile( \
        "tcgen05.ld.sync.aligned.32x32b.x32.b32 " \
        "{%0, %1, %2, %3, %4, %5, %6, %7, " \
        " %8, %9, %10, %11, %12, %13, %14, %15, " \
        " %16, %17, %18, %19, %20, %21, %22, %23, " \
        " %24, %25, %26, %27, %28, %29, %30, %31}, [%32];" \
        : "=r"((r)[0]),  "=r"((r)[1]),  "=r"((r)[2]),  "=r"((r)[3]), \
          "=r"((r)[4]),  "=r"((r)[5]),  "=r"((r)[6]),  "=r"((r)[7]), \
          "=r"((r)[8]),  "=r"((r)[9]),  "=r"((r)[10]), "=r"((r)[11]), \
          "=r"((r)[12]), "=r"((r)[13]), "=r"((r)[14]), "=r"((r)[15]), \
          "=r"((r)[16]), "=r"((r)[17]), "=r"((r)[18]), "=r"((r)[19]), \
          "=r"((r)[20]), "=r"((r)[21]), "=r"((r)[22]), "=r"((r)[23]), \
          "=r"((r)[24]), "=r"((r)[25]), "=r"((r)[26]), "=r"((r)[27]), \
          "=r"((r)[28]), "=r"((r)[29]), "=r"((r)[30]), "=r"((r)[31]) \
        : "r"(ta))
#define TCGEN05_LD_X16(r, ta) \
    asm volatile( \
        "tcgen05.ld.sync.aligned.32x32b.x16.b32 " \
        "{%0, %1, %2, %3, %4, %5, %6, %7, " \
        " %8, %9, %10, %11, %12, %13, %14, %15}, [%16];" \
        : "=r"((r)[0]),  "=r"((r)[1]),  "=r"((r)[2]),  "=r"((r)[3]), \
          "=r"((r)[4]),  "=r"((r)[5]),  "=r"((r)[6]),  "=r"((r)[7]), \
          "=r"((r)[8]),  "=r"((r)[9]),  "=r"((r)[10]), "=r"((r)[11]), \
          "=r"((r)[12]), "=r"((r)[13]), "=r"((r)[14]), "=r"((r)[15]) \
        : "r"(ta))
#define TCGEN05_LD_X8(r, ta) \
    asm volatile( \
        "tcgen05.ld.sync.aligned.32x32b.x8.b32 " \
        "{%0, %1, %2, %3, %4, %5, %6, %7}, [%8];" \
        : "=r"((r)[0]), "=r"((r)[1]), "=r"((r)[2]), "=r"((r)[3]), \
          "=r"((r)[4]), "=r"((r)[5]), "=r"((r)[6]), "=r"((r)[7]) \
        : "r"(ta))

// SS-mode cg1 bf16 MMA: D(TMEM) += A(smem desc) * B(smem desc)^T
__device__ __forceinline__ void mma_f16_ss(uint32_t d_tmem, uint64_t a_desc,
                                           uint64_t b_desc, uint32_t idesc,
                                           uint32_t en) {
    asm volatile(
        "{\n\t.reg .pred p;\n\t"
        "setp.ne.u32 p, %4, 0;\n\t"
        "tcgen05.mma.cta_group::1.kind::f16 [%0], %1, %2, %3, {%5, %5, %5, %5}, p;\n\t}"
        :: "r"(d_tmem), "l"(a_desc), "l"(b_desc), "r"(idesc), "r"(en), "r"(0u)
        : "memory");
}
#endif  // HAS_TCGEN05

static constexpr uint64_t SMEM_DESC_BASE_SW128 =
    (uint64_t(2) << 61) | (uint64_t(1) << 46) | (uint64_t(64) << 32) | (uint64_t(1) << 16);
#define MAKE_SMEM_DESC(a) (SMEM_DESC_BASE_SW128 | ((uint64_t)((a) >> 4) & 0x3FFF))
#define SWZ128(b) ((b) ^ (((b) >> 3) & 0x70))

// idesc: dtype F32(bit4) | atype BF16(bit7) | btype BF16(bit10) | N/8<<17 | M/16<<24
#define IDESC(NV) ((8u << 24) | (((NV) / 8u) << 17) | 0x490u)

__device__ __forceinline__ uint32_t pack_hf2(float a, float b) {
    __half2 p = __float22half2_rn(make_float2(a, b));
    return *(uint32_t*)&p;
}
__device__ __forceinline__ float2 unpack_hf2(unsigned u) {
    return __half22float2(*(__half2*)&u);
}

// ---------------- graph prep ----------------
// edge_index is int32 on device (JAX x64 disabled coerces int64->int32)
__global__ void k_edge_prep(const int* __restrict__ ei) {
    int e = blockIdx.x * blockDim.x + threadIdx.x;
    if (e >= NE) return;
    atomicAdd(&g_indeg[ei[NE + e]], 1);
}
// phase 1: local exclusive scan (1024/block) + block total; also emits dis
__global__ void k_scan_local() {
    __shared__ int warp_sums[32];
    const int tid = threadIdx.x;
    const int v = blockIdx.x * 1024 + tid;
    int val = (v < NN) ? g_indeg[v] : 0;
    if (v < NN) g_dis[v] = rsqrtf((float)(val + 1));   // +1 self-loop
    int x = val;
    #pragma unroll
    for (int o = 1; o < 32; o <<= 1) {
        int y = __shfl_up_sync(0xffffffffu, x, o);
        if ((tid & 31) >= o) x += y;
    }
    if ((tid & 31) == 31) warp_sums[tid >> 5] = x;
    __syncthreads();
    if (tid < 32) {
        int y = warp_sums[tid];
        #pragma unroll
        for (int o = 1; o < 32; o <<= 1) {
            int z = __shfl_up_sync(0xffffffffu, y, o);
            if (tid >= o) y += z;
        }
        warp_sums[tid] = y;
    }
    __syncthreads();
    int warp_prefix = (tid >= 32) ? warp_sums[(tid >> 5) - 1] : 0;
    if (v < NN) g_soff[v] = x + warp_prefix - val;
    if (tid == 0) g_bsum[blockIdx.x] = warp_sums[31];
}
// phase 2 (merged): each block computes its own offset = sum(bsum[0..b-1])
// via a 32-thread reduce (no serial kernel), adds it, inits cursors.
// Block NB-1 also writes the grand total to g_soff[NN].
__global__ void k_scan_add() {
    __shared__ int s_off;
    const int tid = threadIdx.x;
    const int b = blockIdx.x;
    if (tid < 32) {
        int part = 0;
        for (int i = tid; i < b; i += 32) part += g_bsum[i];
        #pragma unroll
        for (int o = 16; o > 0; o >>= 1)
            part += __shfl_xor_sync(0xffffffffu, part, o);
        if (tid == 0) {
            s_off = part;
            if (b == NB - 1) g_soff[NN] = part + g_bsum[b];
        }
    }
    __syncthreads();
    int v = b * 1024 + tid;
    if (v >= NN) return;
    int s = g_soff[v] + s_off;
    g_soff[v] = s;
    g_cursor[v] = s;
}
__global__ void k_scatter(const int* __restrict__ ei) {
    int e = blockIdx.x * blockDim.x + threadIdx.x;
    if (e >= NE) return;
    int r = ei[e];
    int c = ei[NE + e];
    int pos = atomicAdd(&g_cursor[c], 1);
    float nrm = g_dis[r] * g_dis[c];
    g_sedge[pos] = make_uint2((unsigned)r, __float_as_uint(nrm));
}

// ---------------- weight prep (both layers in one launch) -----------------
// B operand layout [Np rows(N), Kp cols(K)], atom = 8n x 64k (1024B):
// off = (n/8 + (k/64)*(Np/8))*512 + (n%8)*64 + (k%64)
__global__ void k_prep_w(const float* __restrict__ W1, const float* __restrict__ W2) {
    int idx = blockIdx.x * blockDim.x + threadIdx.x;
    const float* W;
    __nv_bfloat16 *hi, *lo;
    int K, N, Kp, Np;
    if (idx < W1_ELEMS) {
        W = W1; hi = g_w1hi; lo = g_w1lo; K = F0; N = F1; Kp = L1_KP; Np = L1_NP;
    } else if (idx < W1_ELEMS + W2_ELEMS) {
        idx -= W1_ELEMS;
        W = W2; hi = g_w2hi; lo = g_w2lo; K = F1; N = F2; Kp = L2_KP; Np = L2_NP;
    } else return;
    int n = idx / Kp, k = idx % Kp;
    float v = (n < N && k < K) ? W[(size_t)k * N + n] : 0.f;
    __nv_bfloat16 h = __float2bfloat16(v);
    __nv_bfloat16 l = __float2bfloat16(v - __bfloat162float(h));
    int off = ((n >> 3) + (k >> 6) * (Np >> 3)) * 512 + (n & 7) * 64 + (k & 63);
    hi[off] = h;
    lo[off] = l;
}

// ---------------- CSR aggregation (layer 1, fp32 x, 4-edge unroll) --------
template <int F>
__global__ void k_agg_csr(const float* __restrict__ src, float* __restrict__ dst) {
    int gtid = blockIdx.x * blockDim.x + threadIdx.x;
    int v    = gtid >> 5;
    int lane = gtid & 31;
    if (v >= NN) return;
    constexpr int NA = (F + 31) / 32;
    float acc[NA];
    float d = g_dis[v];
    const float* selfp = src + (size_t)v * F;
    #pragma unroll
    for (int i = 0; i < NA; i++) {
        int f = lane + 32 * i;
        acc[i] = (f < F) ? d * d * selfp[f] : 0.f;
    }
    int b  = g_soff[v];
    int e2 = g_soff[v + 1];
    int j = b;
    for (; j + 3 < e2; j += 4) {           // 4-edge unroll: MLP 4
        uint2 p0 = g_sedge[j],     p1 = g_sedge[j + 1];
        uint2 p2 = g_sedge[j + 2], p3 = g_sedge[j + 3];
        const float* s0 = src + (size_t)p0.x * F;
        const float* s1 = src + (size_t)p1.x * F;
        const float* s2 = src + (size_t)p2.x * F;
        const float* s3 = src + (size_t)p3.x * F;
        float w0 = __uint_as_float(p0.y), w1 = __uint_as_float(p1.y);
        float w2 = __uint_as_float(p2.y), w3 = __uint_as_float(p3.y);
        #pragma unroll
        for (int i = 0; i < NA; i++) {
            int f = lane + 32 * i;
            if (f < F) {
                float a0 = s0[f], a1 = s1[f], a2 = s2[f], a3 = s3[f];
                acc[i] += w0 * a0;
                acc[i] += w1 * a1;
                acc[i] += w2 * a2;
                acc[i] += w3 * a3;
            }
        }
    }
    for (; j < e2; j++) {
        uint2 pe = g_sedge[j];
        const float* sp = src + (size_t)pe.x * F;
        float w = __uint_as_float(pe.y);
        #pragma unroll
        for (int i = 0; i < NA; i++) {
            int f = lane + 32 * i;
            if (f < F) acc[i] += w * sp[f];
        }
    }
    float* dp = dst + (size_t)v * F;
    #pragma unroll
    for (int i = 0; i < NA; i++) {
        int f = lane + 32 * i;
        if (f < F) dp[f] = acc[i];
    }
}

// ---- layer-2 aggregation (fp16 h2 rows) fused with layer-3 dot (4-unroll):
// h3p[v] = sum_f relu(agg2[v,f] + b2[f]) * W3[f]
__global__ void k_agg2dot(const unsigned* __restrict__ src,
                          const float* __restrict__ b2,
                          const float* __restrict__ W3) {
    int gtid = blockIdx.x * blockDim.x + threadIdx.x;
    int v    = gtid >> 5;
    int lane = gtid & 31;
    if (v >= NN) return;
    const bool hiOK = lane < 18;           // words 32..49
    float2 a0 = make_float2(0.f, 0.f), a1 = make_float2(0.f, 0.f);
    float d = g_dis[v];
    float d2 = d * d;
    const unsigned* sp = src + (size_t)v * H2W;
    {
        float2 f0 = unpack_hf2(sp[lane]);
        a0.x = d2 * f0.x; a0.y = d2 * f0.y;
        if (hiOK) {
            float2 f1 = unpack_hf2(sp[32 + lane]);
            a1.x = d2 * f1.x; a1.y = d2 * f1.y;
        }
    }
    int b  = g_soff[v];
    int e2 = g_soff[v + 1];
    int j = b;
    for (; j + 3 < e2; j += 4) {           // 4-edge unroll: MLP 4
        uint2 p0 = g_sedge[j],     p1 = g_sedge[j + 1];
        uint2 p2 = g_sedge[j + 2], p3 = g_sedge[j + 3];
        const unsigned* s0 = src + (size_t)p0.x * H2W;
        const unsigned* s1 = src + (size_t)p1.x * H2W;
        const unsigned* s2 = src + (size_t)p2.x * H2W;
        const unsigned* s3 = src + (size_t)p3.x * H2W;
        float w0 = __uint_as_float(p0.y), w1 = __uint_as_float(p1.y);
        float w2 = __uint_as_float(p2.y), w3 = __uint_as_float(p3.y);
        unsigned u0 = s0[lane], u1 = s1[lane], u2 = s2[lane], u3 = s3[lane];
        float2 f0 = unpack_hf2(u0), f1 = unpack_hf2(u1);
        float2 f2 = unpack_hf2(u2), f3 = unpack_hf2(u3);
        a0.x += w0 * f0.x; a0.y += w0 * f0.y;
        a0.x += w1 * f1.x; a0.y += w1 * f1.y;
        a0.x += w2 * f2.x; a0.y += w2 * f2.y;
        a0.x += w3 * f3.x; a0.y += w3 * f3.y;
        if (hiOK) {
            unsigned q0 = s0[32 + lane], q1 = s1[32 + lane];
            unsigned q2 = s2[32 + lane], q3 = s3[32 + lane];
            float2 g0 = unpack_hf2(q0), g1 = unpack_hf2(q1);
            float2 g2 = unpack_hf2(q2), g3 = unpack_hf2(q3);
            a1.x += w0 * g0.x; a1.y += w0 * g0.y;
            a1.x += w1 * g1.x; a1.y += w1 * g1.y;
            a1.x += w2 * g2.x; a1.y += w2 * g2.y;
            a1.x += w3 * g3.x; a1.y += w3 * g3.y;
        }
    }
    for (; j < e2; j++) {
        uint2 pe = g_sedge[j];
        const unsigned* s0 = src + (size_t)pe.x * H2W;
        float w = __uint_as_float(pe.y);
        float2 f0 = unpack_hf2(s0[lane]);
        a0.x += w * f0.x; a0.y += w * f0.y;
        if (hiOK) {
            float2 f1 = unpack_hf2(s0[32 + lane]);
            a1.x += w * f1.x; a1.y += w * f1.y;
        }
    }
    // fused bias + relu + dot(W3) + warp reduce
    int fA = 2 * lane, fB = 64 + 2 * lane;
    float s = fmaxf(a0.x + b2[fA], 0.f) * W3[fA]
            + fmaxf(a0.y + b2[fA + 1], 0.f) * W3[fA + 1];
    if (hiOK)
        s += fmaxf(a1.x + b2[fB], 0.f) * W3[fB]
           + fmaxf(a1.y + b2[fB + 1], 0.f) * W3[fB + 1];
    #pragma unroll
    for (int o = 16; o > 0; o >>= 1)
        s += __shfl_xor_sync(0xffffffffu, s, o);
    if (lane == 0) g_h3p[v] = s;
}

// ================= Fused layer-1+2 tensor GEMM ============================
// Per CTA (128 rows):
//   D1 = agg1_tile @ W1 (TMEM 0..303)   [split-bf16, 3 products]
//   h1  = relu(D1 + b1) split hi/lo -> double-buffered A2 smem (no DRAM)
//   D2 += h1_chunk @ W2_chunk (TMEM 320..423), epilogue(c+1) overlaps MMA(c)
//   h2  = fp16(D2) -> g_h2b (packed half2 rows)
#define F_A2HI0 1024
#define F_A2LO0 17408
#define F_A2HI1 33792
#define F_A2LO1 50176
#define F_B2HI  66560
#define F_B2LO  133120
#define F_A1HI  66560
#define F_A1LO  82944
#define F_B1HI  99328
#define F_B1LO  138240
#define SMEMF   199680

__global__ void __launch_bounds__(256, 1)
k_tgemm12(const float* __restrict__ A, const float* __restrict__ b1,
          unsigned* __restrict__ Cout) {
#if HAS_TCGEN05
    extern __shared__ char smem[];
    uint32_t sb = smem_to_u32(smem);
    int tid = threadIdx.x, wid = tid >> 5, lane = tid & 31;
    int brow = blockIdx.x * 128;

    if (wid == 0) { TCGEN05_ALLOC(sb + 0, 512); TCGEN05_RELINQ(); }
    if (tid == 0) MBARRIER_INIT(sb + 8, 1);
    __syncthreads();
    uint32_t tb = *(volatile uint32_t*)smem;
    const uint32_t tD1 = tb, tD2 = tb + 320;

    // ---- phase 1 fills ----
    for (int i = tid; i < 128 * 64; i += 256) {
        int m = i >> 6, k = i & 63;
        int gm = brow + m;
        float v = (gm < NN && k < F0) ? A[(size_t)gm * F0 + k] : 0.f;
        __nv_bfloat16 h = __float2bfloat16(v);
        __nv_bfloat16 l = __float2bfloat16(v - __bfloat162float(h));
        uint32_t sw = SWZ128((uint32_t)((m << 7) + (k << 1)));
        *(__nv_bfloat16*)(smem + F_A1HI + sw) = h;
        *(__nv_bfloat16*)(smem + F_A1LO + sw) = l;
    }
    for (int i = tid; i < W1_ELEMS / 8; i += 256) {
        uint4 h = ((const uint4*)g_w1hi)[i];
        uint4 l = ((const uint4*)g_w1lo)[i];
        uint32_t sw = SWZ128((uint32_t)(i * 16));
        *(uint4*)(smem + F_B1HI + sw) = h;
        *(uint4*)(smem + F_B1LO + sw) = l;
    }
    FENCE_ASYNC();
    __syncthreads();

    // ---- MMA1 (commit idx 0) ----
    if (wid == 0 && elect_one_pred()) {
        uint64_t ah = MAKE_SMEM_DESC(sb + F_A1HI);
        uint64_t al = MAKE_SMEM_DESC(sb + F_A1LO);
        uint64_t bh = MAKE_SMEM_DESC(sb + F_B1HI);
        uint64_t bl = MAKE_SMEM_DESC(sb + F_B1LO);
        const uint32_t id0 = IDESC(256), id1 = IDESC(48);
        #pragma unroll
        for (int s = 0; s < 4; s++) {
            uint32_t en = (s > 0);
            mma_f16_ss(tD1,       ah + 2 * s, bh + 2 * s,        id0, en);
            mma_f16_ss(tD1 + 256, ah + 2 * s, bh + 2048 + 2 * s, id1, en);
            mma_f16_ss(tD1,       ah + 2 * s, bl + 2 * s,        id0, 1);
            mma_f16_ss(tD1 + 256, ah + 2 * s, bl + 2048 + 2 * s, id1, 1);
            mma_f16_ss(tD1,       al + 2 * s, bh + 2 * s,        id0, 1);
            mma_f16_ss(tD1 + 256, al + 2 * s, bh + 2048 + 2 * s, id1, 1);
        }
        TCGEN05_COMMIT(sb + 8);
    }
    mbar_wait(sb + 8, 0);           // wait commit 0 (parity 0)
    TCGEN05_FENCE_AFTER();
    __syncthreads();                // A1/B1 dead from here

    // ---- B2 fill (overwrites phase-1 region) ----
    for (int i = tid; i < W2_ELEMS / 8; i += 256) {
        uint4 h = ((const uint4*)g_w2hi)[i];
        uint4 l = ((const uint4*)g_w2lo)[i];
        uint32_t sw = SWZ128((uint32_t)(i * 16));
        *(uint4*)(smem + F_B2HI + sw) = h;
        *(uint4*)(smem + F_B2LO + sw) = l;
    }

    // ---- pipelined chunk loop (double-buffered A2) ----
    // commit idx for chunk c = c+1. Epilogue of chunk c (c>=2) waits commit
    // idx c-1. Waits alternate parity strictly: p0, p1, p0, p1, p0, p1.
    const uint64_t a2h[2] = { MAKE_SMEM_DESC(sb + F_A2HI0), MAKE_SMEM_DESC(sb + F_A2HI1) };
    const uint64_t a2l[2] = { MAKE_SMEM_DESC(sb + F_A2LO0), MAKE_SMEM_DESC(sb + F_A2LO1) };
    const uint64_t b2h = MAKE_SMEM_DESC(sb + F_B2HI);
    const uint64_t b2l = MAKE_SMEM_DESC(sb + F_B2LO);
    const uint32_t id2 = IDESC(104);

    for (int c = 0; c < 5; c++) {
        if (c >= 2) mbar_wait(sb + 8, (uint32_t)((c - 1) & 1));  // idx c-1
        const int buf = c & 1;
        char* a2hi_p = smem + F_A2HI0 + buf * 32768;
        char* a2lo_p = smem + F_A2LO0 + buf * 32768;
        if (wid < 4) {
            int row = wid * 32 + lane;
            uint32_t r[64];
            if (c < 4) {
                TCGEN05_LD_X32(r,      tD1 + 64 * c);
                TCGEN05_LD_X32(r + 32, tD1 + 64 * c + 32);
            } else {
                TCGEN05_LD_X32(r,      tD1 + 256);
                TCGEN05_LD_X16(r + 32, tD1 + 288);
            }
            TCGEN05_WAIT_LD();
            #pragma unroll
            for (int j = 0; j < 64; j += 2) {
                int gc = 64 * c + j;
                float v0 = (gc     < F1) ? fmaxf(__uint_as_float(r[j])     + b1[gc],     0.f) : 0.f;
                float v1 = (gc + 1 < F1) ? fmaxf(__uint_as_float(r[j + 1]) + b1[gc + 1], 0.f) : 0.f;
                __nv_bfloat16 h0 = __float2bfloat16(v0);
                __nv_bfloat16 h1b = __float2bfloat16(v1);
                __nv_bfloat16 l0 = __float2bfloat16(v0 - __bfloat162float(h0));
                __nv_bfloat16 l1 = __float2bfloat16(v1 - __bfloat162float(h1b));
                __nv_bfloat162 ph = __halves2bfloat162(h0, h1b);
                __nv_bfloat162 pl = __halves2bfloat162(l0, l1);
                uint32_t sw = SWZ128((uint32_t)((row << 7) + (j << 1)));
                *(uint32_t*)(a2hi_p + sw) = *(uint32_t*)&ph;
                *(uint32_t*)(a2lo_p + sw) = *(uint32_t*)&pl;
            }
        }
        FENCE_ASYNC();
        __syncthreads();   // A2[buf] ready; also covers B2 fill before chunk 0

        if (wid == 0 && elect_one_pred()) {
            uint32_t boff = c * 832;   // atom-col stride: 13 atoms * 1024B / 16
            #pragma unroll
            for (int s = 0; s < 4; s++) {
                uint32_t aoff = 2 * s, ko = boff + 2 * s;
                mma_f16_ss(tD2, a2h[buf] + aoff, b2h + ko, id2, (c > 0 || s > 0) ? 1u : 0u);
                mma_f16_ss(tD2, a2h[buf] + aoff, b2l + ko, id2, 1);
                mma_f16_ss(tD2, a2l[buf] + aoff, b2h + ko, id2, 1);
            }
            TCGEN05_COMMIT(sb + 8);    // commit idx c+1
        }
        // no wait here — next epilogue writes the other buffer
    }
    mbar_wait(sb + 8, 0);   // commit idx 4 (chunk 3)
    mbar_wait(sb + 8, 1);   // commit idx 5 (chunk 4)
    TCGEN05_FENCE_AFTER();
    __syncthreads();

    // ---- final epilogue: D2 -> packed half2 rows -> g_h2b ----
    uint32_t* stg = (uint32_t*)(smem + 1024);   // 128 x H2W u32 (A2 region dead)
    if (wid < 4) {
        int row = wid * 32 + lane;
        uint32_t r[32];
        #pragma unroll
        for (int g = 0; g < 3; g++) {
            TCGEN05_LD_X32(r, tD2 + g * 32);
            TCGEN05_WAIT_LD();
            #pragma unroll
            for (int j = 0; j < 32; j += 2) {
                int w = (g * 32 + j) >> 1;
                stg[row * H2W + w] = pack_hf2(__uint_as_float(r[j]),
                                              __uint_as_float(r[j + 1]));
            }
        }
        TCGEN05_LD_X8(r, tD2 + 96);
        TCGEN05_WAIT_LD();
        stg[row * H2W + 48] = pack_hf2(__uint_as_float(r[0]), __uint_as_float(r[1]));
        stg[row * H2W + 49] = pack_hf2(__uint_as_float(r[2]), __uint_as_float(r[3]));
    }
    __syncthreads();
    for (int i = tid; i < 128 * 50; i += 256) {
        int m = i / 50, w = i - m * 50;
        int gm = brow + m;
        if (gm < NN) Cout[(size_t)gm * H2W + w] = stg[m * H2W + w];
    }
    __syncthreads();
    if (tid == 0) MBARRIER_INVAL(sb + 8);
    __syncthreads();
    if (wid == 0) TCGEN05_DEALLOC(tb, 512);
#endif
}

// ---------------- final output: CSR aggregate of h3p ----------------------
__global__ void k_out_csr(float* __restrict__ out, const float* __restrict__ b3) {
    int v = blockIdx.x * blockDim.x + threadIdx.x;
    if (v >= NN) return;
    float d = g_dis[v];
    float s = d * d * g_h3p[v];
    int b  = g_soff[v];
    int e2 = g_soff[v + 1];
    for (int j = b; j < e2; j++) {
        uint2 pe = g_sedge[j];
        s += __uint_as_float(pe.y) * g_h3p[pe.x];
    }
    out[v] = s + b3[0];
}

// ---------------- launch ----------------
extern "C" void kernel_launch(void* const* d_in, const int* in_sizes, int n_in,
                              void* d_out, int out_size) {
    const float* x  = (const float*)d_in[0];
    const int*   ei = (const int*)d_in[1];
    const float* W1 = (const float*)d_in[2];
    const float* b1 = (const float*)d_in[3];
    const float* W2 = (const float*)d_in[4];
    const float* b2 = (const float*)d_in[5];
    const float* W3 = (const float*)d_in[6];
    const float* b3 = (const float*)d_in[7];
    float* out = (float*)d_out;

    const int T = 256;
    float*    agg1 = nullptr; cudaGetSymbolAddress((void**)&agg1, g_agg1);
    unsigned* h2b  = nullptr; cudaGetSymbolAddress((void**)&h2b,  g_h2b);
    int*      degp = nullptr; cudaGetSymbolAddress((void**)&degp, g_indeg);

    cudaFuncSetAttribute(k_tgemm12, cudaFuncAttributeMaxDynamicSharedMemorySize, SMEMF);

    // weight prep (both layers, one launch; graph-independent)
    k_prep_w<<<(W1_ELEMS + W2_ELEMS + T - 1) / T, T>>>(W1, W2);

    // CSR build (2-launch scan: local + merged offset/add)
    cudaMemsetAsync(degp, 0, NN * sizeof(int));
    k_edge_prep<<<(NE + T - 1) / T, T>>>(ei);
    k_scan_local<<<NB, 1024>>>();
    k_scan_add<<<NB, 1024>>>();
    k_scatter<<<(NE + T - 1) / T, T>>>(ei);

    const unsigned aggGrid = (unsigned)(((long long)NN * 32 + T - 1) / T);

    // Layers 1+2 fused: aggregate(58, fp32 gather) -> [GEMM1+relu+GEMM2] -> h2b
    k_agg_csr<F0><<<aggGrid, T>>>(x, agg1);
    k_tgemm12<<<MTILES, 256, SMEMF>>>(agg1, b1, h2b);

    // Layer-2 aggregation (fp16 gather, 4-edge unroll) fused with layer-3 dot
    k_agg2dot<<<aggGrid, T>>>(h2b, b2, W3);
    k_out_csr<<<(NN + T - 1) / T, T>>>(out, b3);

    (void)in_sizes; (void)n_in; (void)out_size;
}